// round 12
// baseline (speedup 1.0000x reference)
#include <cuda_runtime.h>
#include <cstdint>

// CoordsToNRF: out[b, p] = atoms_flat[p] * (AU2KCALMOLA / MAX_NRF) / ||c_i - c_j||^2
// p = i*(i-1)/2 + j over the strict lower triangle of 128 atoms. B=2048, NC2=8128.
//
// Round-12: 4 batches per block in packed f32x2 (two lane-pairs). One warp-row
// = 128 outputs sharing one atoms LDG, one address reg (+NC2 immediates), one
// predicate. Rows halved across 2 blocks per batch-group to keep ~55 warps/SM.
// Partial vs full rows split into separate loops (warp-uniform, no divergence).

#define N_ATOMS 128
#define NC2     8128
#define BLOCK_THREADS 256      // 8 warps; block = 4 batches x half the rows

typedef unsigned long long u64;

__device__ __forceinline__ u64 f2_add(u64 a, u64 b) {
    u64 r; asm("add.rn.f32x2 %0, %1, %2;" : "=l"(r) : "l"(a), "l"(b)); return r;
}
__device__ __forceinline__ u64 f2_mul(u64 a, u64 b) {
    u64 r; asm("mul.rn.f32x2 %0, %1, %2;" : "=l"(r) : "l"(a), "l"(b)); return r;
}
__device__ __forceinline__ u64 f2_fma(u64 a, u64 b, u64 c) {
    u64 r; asm("fma.rn.f32x2 %0, %1, %2, %3;" : "=l"(r) : "l"(a), "l"(b), "l"(c)); return r;
}
__device__ __forceinline__ float2 f2_lohi(u64 v) {
    float2 f; asm("mov.b64 {%0, %1}, %2;" : "=f"(f.x), "=f"(f.y) : "l"(v)); return f;
}

__device__ __forceinline__ float nrf_scale() {
    return (float)(627.5095 * 0.529177 / 100.0);
}

__global__ __launch_bounds__(BLOCK_THREADS, 6)
void coords_to_nrf_kernel(const float* __restrict__ coords,
                          const float* __restrict__ atoms_flat,
                          float* __restrict__ out) {
    // Per atom: {x0,x1,x2,x3, y0,y1,y2,y3, z0,z1,z2,z3} = 48B record. 6KB total.
    __shared__ __align__(16) float sc[N_ATOMS * 12];

    const int warp  = threadIdx.x >> 5;   // 0..7 -> row chunk
    const int lane  = threadIdx.x & 31;
    const int group = blockIdx.x >> 1;    // batch group of 4
    const int half  = blockIdx.x & 1;     // row half

    // ---- Stage 4 batches' coords (gmem [b][atom][3] -> 48B records) ----
    const float* cb = coords + (size_t)group * 4 * (N_ATOMS * 3);
    #pragma unroll
    for (int idx = threadIdx.x; idx < 4 * N_ATOMS * 3; idx += BLOCK_THREADS) {
        const int q   = idx / (N_ATOMS * 3);       // batch in group
        const int rem = idx - q * (N_ATOMS * 3);
        const int a   = rem / 3;
        const int d   = rem - a * 3;
        sc[a * 12 + d * 4 + q] = cb[idx];
    }
    __syncthreads();

    const float scale = nrf_scale();
    const u64 S = 0x8000000080000000ull;           // packed f32x2 sign flip

    // Rows [0,316) halved; each half (158 rows) split 20,20,20,20,20,20,19,19.
    const int base = (warp < 6) ? warp * 20 : (120 + (warp - 6) * 19);
    const int cnt  = (warp < 6) ? 20 : 19;
    const int r0 = half * 158 + base;
    const int r1 = r0 + cnt;

    const int starts[5] = {0, 127, 222, 285, 316};

    float* ob = out + (size_t)group * 4 * NC2;     // batch q=0 plane

    #pragma unroll
    for (int seg = 0; seg < 4; seg++) {
        const int a = (r0 > starts[seg])     ? r0 : starts[seg];
        const int b = (r1 < starts[seg + 1]) ? r1 : starts[seg + 1];
        if (a >= b) continue;

        const int j0 = seg * 32;
        const int j  = j0 + lane;

        // cj record as three 16B lane loads, negated once.
        const float* cjr = &sc[j * 12];
        const ulonglong2 cjx = *reinterpret_cast<const ulonglong2*>(cjr);      // x01,x23
        const ulonglong2 cjy = *reinterpret_cast<const ulonglong2*>(cjr + 4);  // y01,y23
        const ulonglong2 cjz = *reinterpret_cast<const ulonglong2*>(cjr + 8);  // z01,z23
        const u64 nx0 = cjx.x ^ S, nx1 = cjx.y ^ S;
        const u64 ny0 = cjy.x ^ S, ny1 = cjy.y ^ S;
        const u64 nz0 = cjz.x ^ S, nz1 = cjz.y ^ S;

        const int i_start = j0 + 1 + (a - starts[seg]);
        const int i_end   = i_start + (b - a);
        // Partial rows: i < j0+32 (per-lane masking). Full rows: i >= j0+32.
        const int i_mid_raw = j0 + 32;
        const int i_mid = (i_end < i_mid_raw) ? i_end
                        : ((i_start > i_mid_raw) ? i_start : i_mid_raw);

        int pbase = (i_start * (i_start - 1)) >> 1;

        // ---- partial rows (diagonal band), predicated stores ----
        #pragma unroll 2
        for (int i = i_start; i < i_mid; i++) {
            const float* cir = &sc[i * 12];
            const ulonglong2 cix = *reinterpret_cast<const ulonglong2*>(cir);
            const ulonglong2 ciy = *reinterpret_cast<const ulonglong2*>(cir + 4);
            const ulonglong2 ciz = *reinterpret_cast<const ulonglong2*>(cir + 8);

            const u64 dx0 = f2_add(cix.x, nx0), dx1 = f2_add(cix.y, nx1);
            const u64 dy0 = f2_add(ciy.x, ny0), dy1 = f2_add(ciy.y, ny1);
            const u64 dz0 = f2_add(ciz.x, nz0), dz1 = f2_add(ciz.y, nz1);
            const u64 dA = f2_fma(dz0, dz0, f2_fma(dy0, dy0, f2_mul(dx0, dx0)));
            const u64 dB = f2_fma(dz1, dz1, f2_fma(dy1, dy1, f2_mul(dx1, dx1)));

            const float2 a01 = f2_lohi(dA);
            const float2 a23 = f2_lohi(dB);

            const int p  = pbase + j;
            const int pc = (p < NC2 - 1) ? p : (NC2 - 1);  // masked-lane safety
            const float aval = __ldg(&atoms_flat[pc]) * scale;
            const float v0 = __fdividef(aval, a01.x);
            const float v1 = __fdividef(aval, a01.y);
            const float v2 = __fdividef(aval, a23.x);
            const float v3 = __fdividef(aval, a23.y);

            if (j < i) {
                float* o = ob + p;
                o[0]       = v0;
                o[NC2]     = v1;
                o[2 * NC2] = v2;
                o[3 * NC2] = v3;
            }
            pbase += i;
        }

        // ---- full rows, unconditional stores ----
        #pragma unroll 2
        for (int i = i_mid; i < i_end; i++) {
            const float* cir = &sc[i * 12];
            const ulonglong2 cix = *reinterpret_cast<const ulonglong2*>(cir);
            const ulonglong2 ciy = *reinterpret_cast<const ulonglong2*>(cir + 4);
            const ulonglong2 ciz = *reinterpret_cast<const ulonglong2*>(cir + 8);

            const u64 dx0 = f2_add(cix.x, nx0), dx1 = f2_add(cix.y, nx1);
            const u64 dy0 = f2_add(ciy.x, ny0), dy1 = f2_add(ciy.y, ny1);
            const u64 dz0 = f2_add(ciz.x, nz0), dz1 = f2_add(ciz.y, nz1);
            const u64 dA = f2_fma(dz0, dz0, f2_fma(dy0, dy0, f2_mul(dx0, dx0)));
            const u64 dB = f2_fma(dz1, dz1, f2_fma(dy1, dy1, f2_mul(dx1, dx1)));

            const float2 a01 = f2_lohi(dA);
            const float2 a23 = f2_lohi(dB);

            const int p = pbase + j;                       // always valid here
            const float aval = __ldg(&atoms_flat[p]) * scale;

            float* o = ob + p;
            o[0]       = __fdividef(aval, a01.x);
            o[NC2]     = __fdividef(aval, a01.y);
            o[2 * NC2] = __fdividef(aval, a23.x);
            o[3 * NC2] = __fdividef(aval, a23.y);
            pbase += i;
        }
    }
}

extern "C" void kernel_launch(void* const* d_in, const int* in_sizes, int n_in,
                              void* d_out, int out_size) {
    const float* coords     = (const float*)d_in[0];  // [2048, 128, 3] f32
    const float* atoms_flat = (const float*)d_in[1];  // [8128] f32
    float* out = (float*)d_out;                       // [2048, 8128] f32

    const int batch = in_sizes[0] / (N_ATOMS * 3);    // 2048
    coords_to_nrf_kernel<<<(batch / 4) * 2, BLOCK_THREADS>>>(coords, atoms_flat, out);
}